// round 9
// baseline (speedup 1.0000x reference)
#include <cuda_runtime.h>
#include <cstdint>

#define SEQ 2048
#define NB 64
#define NF 16
#define HD 512
#define ROWB 2048                        // bytes per hidden row (gmem)
#define ROWP 2064                        // staged row stride (129 16B-units, ≡1 mod 8)
#define SLOT_PAD 516                     // floats per f-row (129 units): conflict-free
#define SLOT_BYTES (NF * SLOT_PAD * 4)   // 33024
#define U_TOK 32                         // tokens per unit = rows per stage
#define STAGE_B (U_TOK * ROWP)           // 66048
#define CNT_OFF (SLOT_BYTES + 2 * STAGE_B)   // 165120
#define SMEM_TOTAL (CNT_OFF + NB * 4)        // 165376 -> 1 block/SM
#define N_UNITS ((SEQ / U_TOK) * NB)     // 4096, u = x*64 + b
#define GRID_X 148                       // 1/SM, single wave

// Scratch (allocation-free rule: __device__ globals)
__device__ int g_list[NB * SEQ];   // packed: token_pos | (seg << 16), compacted per batch
__device__ int g_cnt[NB];

__device__ __forceinline__ unsigned long long ffma2(unsigned long long a,
                                                    unsigned long long b,
                                                    unsigned long long c) {
    unsigned long long d;
    asm("fma.rn.f32x2 %0, %1, %2, %3;" : "=l"(d) : "l"(a), "l"(b), "l"(c));
    return d;
}

__device__ __forceinline__ void cp16(unsigned dst_smem, const void* src) {
    asm volatile("cp.async.cg.shared.global [%0], [%1], 16;" :: "r"(dst_smem), "l"(src));
}
__device__ __forceinline__ void cp_commit() {
    asm volatile("cp.async.commit_group;");
}
template <int N>
__device__ __forceinline__ void cp_wait() {
    asm volatile("cp.async.wait_group %0;" :: "n"(N));
}

// ---------------------------------------------------------------------------
// Block-wide exclusive scan over 256 threads
// ---------------------------------------------------------------------------
__device__ __forceinline__ int block_exscan(int v, int* sh) {
    int lane = threadIdx.x & 31;
    int w = threadIdx.x >> 5;
    int incl = v;
#pragma unroll
    for (int o = 1; o < 32; o <<= 1) {
        int n = __shfl_up_sync(0xFFFFFFFFu, incl, o);
        if (lane >= o) incl += n;
    }
    if (lane == 31) sh[w] = incl;
    __syncthreads();
    if (threadIdx.x < 8) {
        int x = sh[threadIdx.x];
#pragma unroll
        for (int o = 1; o < 8; o <<= 1) {
            int n = __shfl_up_sync(0xFFu, x, o);
            if (threadIdx.x >= (unsigned)o) x += n;
        }
        sh[threadIdx.x] = x;
    }
    __syncthreads();
    int wofs = (w == 0) ? 0 : sh[w - 1];
    return wofs + incl - v;
}

// ---------------------------------------------------------------------------
// Kernel 1 (fused): zero output (all 256 blocks) + per-batch span ids +
// compaction (first 64 blocks).
// ---------------------------------------------------------------------------
__global__ __launch_bounds__(256) void seg_zero_kernel(const int* __restrict__ labels,
                                                       const int* pB, const int* pI,
                                                       const int* pMS,
                                                       float* __restrict__ out,
                                                       int out_n) {
    {
        int tid = blockIdx.x * 256 + threadIdx.x;
        int nthreads = gridDim.x * 256;
        int n4 = out_n >> 2;
        float4 z = make_float4(0.f, 0.f, 0.f, 0.f);
        for (int i = tid; i < n4; i += nthreads)
            reinterpret_cast<float4*>(out)[i] = z;
        for (int i = (n4 << 2) + tid; i < out_n; i += nthreads)
            out[i] = 0.0f;
    }
    if (blockIdx.x >= NB) return;

    __shared__ int sh[8];
    int b = blockIdx.x;
    int t = threadIdx.x;
    int Bv = pB ? *pB : 1;
    int Iv = pI ? *pI : 2;
    int MS = pMS ? *pMS : 512;

    const int4* row = reinterpret_cast<const int4*>(labels + b * SEQ) + t * 2;
    int4 a = row[0];
    int4 c = row[1];
    int lab[8] = {a.x, a.y, a.z, a.w, c.x, c.y, c.z, c.w};

    int incl[8];
    int csum = 0;
#pragma unroll
    for (int i = 0; i < 8; i++) {
        csum += (lab[i] == Bv);
        incl[i] = csum;
    }
    int ex = block_exscan(csum, sh);

    int seg[8], vfl[8];
    int vtot = 0;
#pragma unroll
    for (int i = 0; i < 8; i++) {
        seg[i] = ex + incl[i] - 1;
        vfl[i] = ((lab[i] == Bv) || (lab[i] == Iv)) && seg[i] >= 0 && seg[i] < MS;
        vtot += vfl[i];
    }
    __syncthreads();
    int vex = block_exscan(vtot, sh);

    int pos = vex;
#pragma unroll
    for (int i = 0; i < 8; i++) {
        if (vfl[i]) {
            g_list[b * SEQ + pos] = (t * 8 + i) | (seg[i] << 16);
            pos++;
        }
    }
    if (t == 255) g_cnt[b] = vex + vtot;
}

// ---------------------------------------------------------------------------
// Kernel 2: block-cooperative gather-projection with WHOLE-ROW DRAM bursts.
//
// Unit = 32 compacted tokens of batch b (u = x*64 + b), one unit per block
// stage. Stage buffer = 32 full 2KB rows (2064B stride). Ring 2, barrier
// pipelined, issue-ahead one unit.
//
// LOAD (decoupled from compute split): warp w loads rows 4w..4w+3, each as
// 4 back-to-back cp16 covering the row's 2048B contiguously -> HBM sees
// clean 2KB bursts instead of scattered 64B fragments.
//
// COMPUTE: warp (q = w&3, h = w>>2) takes d-quarter q of tokens
// [16h, 16h+16). Lane (tg = l>>3, fh = l&7) tiles tokens {tg,tg+4,tg+8,tg+12}
// (half-local) x f = {fh, fh+8}: per 16B d-chunk 6 LDS.128 (all broadcast/
// conflict-free) feed 16 FFMA2. acc = 16 regs. Quarter-d partial sums
// scatter via atomicAdd (4 partials per (tok,f)).
// ---------------------------------------------------------------------------
__global__ __launch_bounds__(256, 1) void proj_kernel(const float* __restrict__ hidden,
                                                      const float* __restrict__ slot,
                                                      const int* pMS,
                                                      float* __restrict__ out) {
    extern __shared__ float smem[];
    float* slot_sh = smem;
    char* smem_bytes = reinterpret_cast<char*>(smem);
    int* cnts = reinterpret_cast<int*>(smem_bytes + CNT_OFF);
    int MS = pMS ? *pMS : 512;

    unsigned smem_base = (unsigned)__cvta_generic_to_shared(smem);
    unsigned stage_s[2] = {smem_base + SLOT_BYTES, smem_base + SLOT_BYTES + STAGE_B};
    const char* stage_g[2] = {smem_bytes + SLOT_BYTES, smem_bytes + SLOT_BYTES + STAGE_B};

    // stage slot_embs transposed: slot_sh[f][d]; cache per-batch counts
    for (int i = threadIdx.x; i < HD * NF; i += 256) {
        int d = i >> 4;
        int f = i & 15;
        slot_sh[f * SLOT_PAD + d] = slot[i];
    }
    if (threadIdx.x < NB) cnts[threadIdx.x] = g_cnt[threadIdx.x];
    __syncthreads();

    int w = threadIdx.x >> 5;
    int lane = threadIdx.x & 31;
    int q = w & 3;            // compute: d-quarter
    int h = w >> 2;           // compute: token half
    int tg = lane >> 3;       // compute: token group (0..3)
    int fh = lane & 7;        // compute: f half (0..7)

    const char* hbytes = reinterpret_cast<const char*>(hidden);

    // valid-unit cursor walk (uniform across the block)
    auto next_valid = [&](int u) {
        while (u < N_UNITS && (u >> 6) * U_TOK >= cnts[u & 63]) u += GRID_X;
        return u;
    };

    // issue one unit's stage: this warp loads rows 4w..4w+3, whole rows
    auto issue = [&](int u, unsigned buf) {
        int x = u >> 6;
        int b = u & 63;
        int cnt = cnts[b];
        int t0 = x * U_TOK;
        const int* lst = g_list + b * SEQ;
#pragma unroll
        for (int j = 0; j < 4; j++) {
            int r = 4 * w + j;
            int ti = t0 + r;
            if (ti >= cnt) ti = cnt - 1;
            unsigned rofs = ((unsigned)b * SEQ + (unsigned)(lst[ti] & 0xFFFF)) * ROWB;
            unsigned dst = buf + r * ROWP + lane * 16;
            const char* src = hbytes + rofs + lane * 16;
#pragma unroll
            for (int k = 0; k < 4; k++)
                cp16(dst + k * 512, src + k * 512);
        }
        cp_commit();
    };

    auto compute = [&](int u, const char* buf) {
        int x = u >> 6;
        int b = u & 63;
        int cnt = cnts[b];
        int t0 = x * U_TOK;

        const float* s0p = slot_sh + fh * SLOT_PAD + q * 128;
        const float* s1p = s0p + 8 * SLOT_PAD;
        const char* hrow[4];
#pragma unroll
        for (int j = 0; j < 4; j++)
            hrow[j] = buf + (h * 16 + tg + 4 * j) * ROWP + q * 512;

        unsigned long long acc[4][2];
#pragma unroll
        for (int j = 0; j < 4; j++) {
            acc[j][0] = 0ull;
            acc[j][1] = 0ull;
        }

#pragma unroll 8
        for (int c = 0; c < 32; c++) {
            ulonglong2 S0 = *reinterpret_cast<const ulonglong2*>(s0p + c * 4);
            ulonglong2 S1 = *reinterpret_cast<const ulonglong2*>(s1p + c * 4);
#pragma unroll
            for (int j = 0; j < 4; j++) {
                ulonglong2 H = *reinterpret_cast<const ulonglong2*>(hrow[j] + c * 16);
                acc[j][0] = ffma2(H.x, S0.x, acc[j][0]);
                acc[j][0] = ffma2(H.y, S0.y, acc[j][0]);
                acc[j][1] = ffma2(H.x, S1.x, acc[j][1]);
                acc[j][1] = ffma2(H.y, S1.y, acc[j][1]);
            }
        }

        const int* lst = g_list + b * SEQ;
#pragma unroll
        for (int j = 0; j < 4; j++) {
            int ti = t0 + h * 16 + tg + 4 * j;
            if (ti < cnt) {
                int p = lst[ti];
                float* op = out + ((size_t)b * MS + (p >> 16)) * NF;
                float2 v0 = *reinterpret_cast<float2*>(&acc[j][0]);
                float2 v1 = *reinterpret_cast<float2*>(&acc[j][1]);
                atomicAdd(op + fh, v0.x + v0.y);
                atomicAdd(op + fh + 8, v1.x + v1.y);
            }
        }
    };

    int u_cur = next_valid(blockIdx.x);
    if (u_cur >= N_UNITS) return;   // uniform: whole block exits together

    issue(u_cur, stage_s[0]);
    int u_next = next_valid(u_cur + GRID_X);
    int slot_id = 0;

    for (;;) {
        if (u_next < N_UNITS) {
            issue(u_next, stage_s[slot_id ^ 1]);
            cp_wait<1>();           // current stage landed; next still in flight
        } else {
            cp_wait<0>();
        }
        __syncthreads();            // publish all warps' rows for this stage
        compute(u_cur, stage_g[slot_id]);
        __syncthreads();            // stage fully consumed before refill
        if (u_next >= N_UNITS) break;
        u_cur = u_next;
        u_next = next_valid(u_next + GRID_X);
        slot_id ^= 1;
    }
}

// ---------------------------------------------------------------------------
extern "C" void kernel_launch(void* const* d_in, const int* in_sizes, int n_in,
                              void* d_out, int out_size) {
    const float* hidden = (const float*)d_in[0];
    const float* slot = (const float*)d_in[1];
    const int* labels = (const int*)d_in[2];
    const int* pB = (n_in > 3) ? (const int*)d_in[3] : nullptr;
    const int* pI = (n_in > 4) ? (const int*)d_in[4] : nullptr;
    const int* pMS = (n_in > 5) ? (const int*)d_in[5] : nullptr;
    float* out = (float*)d_out;

    static bool attr_set = false;
    if (!attr_set) {
        cudaFuncSetAttribute(proj_kernel, cudaFuncAttributeMaxDynamicSharedMemorySize,
                             SMEM_TOTAL);
        attr_set = true;
    }

    seg_zero_kernel<<<256, 256>>>(labels, pB, pI, pMS, out, out_size);
    proj_kernel<<<GRID_X, 256, SMEM_TOTAL>>>(hidden, slot, pMS, out);
}

// round 10
// speedup vs baseline: 1.3906x; 1.3906x over previous
#include <cuda_runtime.h>
#include <cstdint>

#define SEQ 2048
#define NB 64
#define NF 16
#define HD 512
#define ROWB 2048                        // bytes per hidden row (gmem)
#define SLOT_PAD 516                     // floats per f-row: 129 units ≡1 mod 8, conflict-free
#define SLOT_BYTES (NF * SLOT_PAD * 4)   // 33024
#define U_TOK 32                         // tokens per unit (block)
#define W_TOK 16                         // tokens per warp
#define TROW 144                         // staged token-row stride (9 units ≡1 mod 8)
#define STAGE_B (W_TOK * TROW)           // 2304
#define RING_STAGES 4
#define NW 8                             // warps/block: 4 d-quarters x 2 token-halves
#define CNT_OFF (SLOT_BYTES + NW * RING_STAGES * STAGE_B)   // 106752
#define SMEM_TOTAL (CNT_OFF + NB * 4)                       // 107008 -> 2 blocks/SM
#define N_UNITS ((SEQ / U_TOK) * NB)     // 4096, u = x*64 + b
#define GRID_X 296                       // 2/SM

// Scratch (allocation-free rule: __device__ globals)
__device__ int g_list[NB * SEQ];   // packed: token_pos | (seg << 16), compacted per batch
__device__ int g_cnt[NB];

__device__ __forceinline__ unsigned long long ffma2(unsigned long long a,
                                                    unsigned long long b,
                                                    unsigned long long c) {
    unsigned long long d;
    asm("fma.rn.f32x2 %0, %1, %2, %3;" : "=l"(d) : "l"(a), "l"(b), "l"(c));
    return d;
}

__device__ __forceinline__ void cp16(void* dst_smem, const void* src) {
    unsigned saddr = (unsigned)__cvta_generic_to_shared(dst_smem);
    asm volatile("cp.async.cg.shared.global [%0], [%1], 16;" :: "r"(saddr), "l"(src));
}
__device__ __forceinline__ void cp_commit() {
    asm volatile("cp.async.commit_group;");
}
template <int N>
__device__ __forceinline__ void cp_wait() {
    asm volatile("cp.async.wait_group %0;" :: "n"(N));
}

// ---------------------------------------------------------------------------
// Block-wide exclusive scan over 256 threads
// ---------------------------------------------------------------------------
__device__ __forceinline__ int block_exscan(int v, int* sh) {
    int lane = threadIdx.x & 31;
    int w = threadIdx.x >> 5;
    int incl = v;
#pragma unroll
    for (int o = 1; o < 32; o <<= 1) {
        int n = __shfl_up_sync(0xFFFFFFFFu, incl, o);
        if (lane >= o) incl += n;
    }
    if (lane == 31) sh[w] = incl;
    __syncthreads();
    if (threadIdx.x < 8) {
        int x = sh[threadIdx.x];
#pragma unroll
        for (int o = 1; o < 8; o <<= 1) {
            int n = __shfl_up_sync(0xFFu, x, o);
            if (threadIdx.x >= (unsigned)o) x += n;
        }
        sh[threadIdx.x] = x;
    }
    __syncthreads();
    int wofs = (w == 0) ? 0 : sh[w - 1];
    return wofs + incl - v;
}

// ---------------------------------------------------------------------------
// Kernel 1 (fused): zero output (all 256 blocks) + per-batch span ids +
// compaction (first 64 blocks).
// ---------------------------------------------------------------------------
__global__ __launch_bounds__(256) void seg_zero_kernel(const int* __restrict__ labels,
                                                       const int* pB, const int* pI,
                                                       const int* pMS,
                                                       float* __restrict__ out,
                                                       int out_n) {
    {
        int tid = blockIdx.x * 256 + threadIdx.x;
        int nthreads = gridDim.x * 256;
        int n4 = out_n >> 2;
        float4 z = make_float4(0.f, 0.f, 0.f, 0.f);
        for (int i = tid; i < n4; i += nthreads)
            reinterpret_cast<float4*>(out)[i] = z;
        for (int i = (n4 << 2) + tid; i < out_n; i += nthreads)
            out[i] = 0.0f;
    }
    if (blockIdx.x >= NB) return;

    __shared__ int sh[8];
    int b = blockIdx.x;
    int t = threadIdx.x;
    int Bv = pB ? *pB : 1;
    int Iv = pI ? *pI : 2;
    int MS = pMS ? *pMS : 512;

    const int4* row = reinterpret_cast<const int4*>(labels + b * SEQ) + t * 2;
    int4 a = row[0];
    int4 c = row[1];
    int lab[8] = {a.x, a.y, a.z, a.w, c.x, c.y, c.z, c.w};

    int incl[8];
    int csum = 0;
#pragma unroll
    for (int i = 0; i < 8; i++) {
        csum += (lab[i] == Bv);
        incl[i] = csum;
    }
    int ex = block_exscan(csum, sh);

    int seg[8], vfl[8];
    int vtot = 0;
#pragma unroll
    for (int i = 0; i < 8; i++) {
        seg[i] = ex + incl[i] - 1;
        vfl[i] = ((lab[i] == Bv) || (lab[i] == Iv)) && seg[i] >= 0 && seg[i] < MS;
        vtot += vfl[i];
    }
    __syncthreads();
    int vex = block_exscan(vtot, sh);

    int pos = vex;
#pragma unroll
    for (int i = 0; i < 8; i++) {
        if (vfl[i]) {
            g_list[b * SEQ + pos] = (t * 8 + i) | (seg[i] << 16);
            pos++;
        }
    }
    if (t == 255) g_cnt[b] = vex + vtot;
}

// ---------------------------------------------------------------------------
// Kernel 2: warp-autonomous gather-projection, flat 4-deep pipeline,
// LINEAR padded stage layout (const-offset LDS, no swizzle math).
//
// Unit = 32 compacted tokens (u = x*64 + b). Warp (q = w&3, h = w>>2) owns
// d-quarter q of tokens [16h, 16h+16). Stage = 16 tokens x 32 d, rows padded
// to 144 B (9 units ≡ 1 mod 8):
//   stores: lane (r4, qq) writes token r4+8m, chunks qq/qq+4:
//           bank = (r4 + qq)&7 -> each bank exactly 4x = minimal wavefronts.
//   reads:  H token t = tg + 4j, chunk c: bank = (t + c)&7, tg in 0..3 ->
//           4 distinct banks, conflict-free; S rows stride 129 ≡ 1 -> free.
// All compute-side LDS addresses are base + compile-time constants.
//
// Issue cursor runs 3 stages ahead of compute through a 4-slot ring; the
// stage stream is continuous across the warp's whole unit list.
// ---------------------------------------------------------------------------
__global__ __launch_bounds__(256, 2) void proj_kernel(const float* __restrict__ hidden,
                                                      const float* __restrict__ slot,
                                                      const int* pMS,
                                                      float* __restrict__ out) {
    extern __shared__ float smem[];
    float* slot_sh = smem;
    char* ringbase = reinterpret_cast<char*>(smem) + SLOT_BYTES;
    int* cnts = reinterpret_cast<int*>(reinterpret_cast<char*>(smem) + CNT_OFF);
    int MS = pMS ? *pMS : 512;

    for (int i = threadIdx.x; i < HD * NF; i += 256) {
        int d = i >> 4;
        int f = i & 15;
        slot_sh[f * SLOT_PAD + d] = slot[i];
    }
    if (threadIdx.x < NB) cnts[threadIdx.x] = g_cnt[threadIdx.x];
    __syncthreads();

    int w = threadIdx.x >> 5;
    int lane = threadIdx.x & 31;
    int q = w & 3;            // d-quarter
    int h = w >> 2;           // token half
    int r4 = lane >> 2;       // staging token group (0..7)
    int qq = lane & 3;        // staging chunk quad (0..3)
    int tg = lane >> 3;       // compute token base (0..3); tokens tg+4j
    int fh = lane & 7;        // compute f half (0..7)
    char* ring0 = ringbase + w * RING_STAGES * STAGE_B;

    // staging dst offsets (unit-invariant, linear layout)
    int dstA[2], dstB[2];
#pragma unroll
    for (int m = 0; m < 2; m++) {
        dstA[m] = (r4 + 8 * m) * TROW + qq * 16;
        dstB[m] = dstA[m] + 64;
    }

    const char* hbase = reinterpret_cast<const char*>(hidden) + q * 512;

    // total stages for this block (uniform across its warps)
    int total = 0;
    for (int u = blockIdx.x; u < N_UNITS; u += GRID_X)
        if ((u >> 6) * U_TOK < cnts[u & 63]) total++;
    if (total == 0) return;
    total *= 4;

    // ---- issue cursor ----
    int u_i = blockIdx.x;
    while ((u_i >> 6) * U_TOK >= cnts[u_i & 63]) u_i += GRID_X;
    unsigned ofs_i[2];
    int s_i = 0;
    int isl = 0;

    auto load_ofs = [&](int u) {
        int x = u >> 6;
        int b = u & 63;
        int cnt = cnts[b];
        int t0 = x * U_TOK + h * W_TOK;
#pragma unroll
        for (int m = 0; m < 2; m++) {
            int ti = t0 + r4 + 8 * m;
            if (ti >= cnt) ti = cnt - 1;
            ofs_i[m] = ((unsigned)b * SEQ + (unsigned)(g_list[b * SEQ + ti] & 0xFFFF)) * ROWB;
        }
    };
    load_ofs(u_i);

    auto issue_one = [&]() {
        char* buf = ring0 + (isl & 3) * STAGE_B;
#pragma unroll
        for (int m = 0; m < 2; m++) {
            const char* src = hbase + ofs_i[m] + s_i * 128;
            cp16(buf + dstA[m], src + qq * 16);
            cp16(buf + dstB[m], src + qq * 16 + 64);
        }
        cp_commit();
        isl++;
        if (++s_i == 4) {
            s_i = 0;
            do {
                u_i += GRID_X;
            } while (u_i < N_UNITS && (u_i >> 6) * U_TOK >= cnts[u_i & 63]);
            if (u_i < N_UNITS) load_ofs(u_i);
        }
    };

    int pre = total < 3 ? total : 3;
    for (int k = 0; k < pre; k++) issue_one();

    // ---- compute cursor ----
    int u_c = blockIdx.x;
    while ((u_c >> 6) * U_TOK >= cnts[u_c & 63]) u_c += GRID_X;

    unsigned long long acc[4][2];
    const float* sbase = slot_sh + fh * SLOT_PAD + q * 128;

    for (int i = 0; i < total; i++) {
        int ahead = total - 1 - i;
        if (ahead >= 2) cp_wait<2>();
        else if (ahead == 1) cp_wait<1>();
        else cp_wait<0>();
        __syncwarp();

        int s = i & 3;
        if (s == 0) {
#pragma unroll
            for (int j = 0; j < 4; j++) {
                acc[j][0] = 0ull;
                acc[j][1] = 0ull;
            }
        }

        // base pointers: all inner offsets are compile-time constants
        const char* hb = ring0 + (i & 3) * STAGE_B + tg * TROW;
        const float* s0p = sbase + s * 32;
        const float* s1p = s0p + 8 * SLOT_PAD;
#pragma unroll
        for (int c = 0; c < 8; c++) {
            ulonglong2 S0 = *reinterpret_cast<const ulonglong2*>(s0p + c * 4);
            ulonglong2 S1 = *reinterpret_cast<const ulonglong2*>(s1p + c * 4);
#pragma unroll
            for (int j = 0; j < 4; j++) {
                // token tg + 4j, chunk c: offset = 4j*144 + 16c (const)
                ulonglong2 H = *reinterpret_cast<const ulonglong2*>(hb + j * (4 * TROW) + c * 16);
                acc[j][0] = ffma2(H.x, S0.x, acc[j][0]);
                acc[j][0] = ffma2(H.y, S0.y, acc[j][0]);
                acc[j][1] = ffma2(H.x, S1.x, acc[j][1]);
                acc[j][1] = ffma2(H.y, S1.y, acc[j][1]);
            }
        }

        if (s == 3) {
            int x = u_c >> 6;
            int b = u_c & 63;
            int cnt = cnts[b];
            int t0 = x * U_TOK + h * W_TOK;
            const int* lst = g_list + b * SEQ;
#pragma unroll
            for (int j = 0; j < 4; j++) {
                int ti = t0 + tg + 4 * j;
                if (ti < cnt) {
                    int p = lst[ti];
                    float* op = out + ((size_t)b * MS + (p >> 16)) * NF;
                    float2 v0 = *reinterpret_cast<float2*>(&acc[j][0]);
                    float2 v1 = *reinterpret_cast<float2*>(&acc[j][1]);
                    atomicAdd(op + fh, v0.x + v0.y);
                    atomicAdd(op + fh + 8, v1.x + v1.y);
                }
            }
            do {
                u_c += GRID_X;
            } while (u_c < N_UNITS && (u_c >> 6) * U_TOK >= cnts[u_c & 63]);
        }

        __syncwarp();   // ring slot fully read before refill
        if (isl < total) issue_one();
    }
}

// ---------------------------------------------------------------------------
extern "C" void kernel_launch(void* const* d_in, const int* in_sizes, int n_in,
                              void* d_out, int out_size) {
    const float* hidden = (const float*)d_in[0];
    const float* slot = (const float*)d_in[1];
    const int* labels = (const int*)d_in[2];
    const int* pB = (n_in > 3) ? (const int*)d_in[3] : nullptr;
    const int* pI = (n_in > 4) ? (const int*)d_in[4] : nullptr;
    const int* pMS = (n_in > 5) ? (const int*)d_in[5] : nullptr;
    float* out = (float*)d_out;

    static bool attr_set = false;
    if (!attr_set) {
        cudaFuncSetAttribute(proj_kernel, cudaFuncAttributeMaxDynamicSharedMemorySize,
                             SMEM_TOTAL);
        attr_set = true;
    }

    seg_zero_kernel<<<256, 256>>>(labels, pB, pI, pMS, out, out_size);
    proj_kernel<<<GRID_X, 256, SMEM_TOTAL>>>(hidden, slot, pMS, out);
}